// round 15
// baseline (speedup 1.0000x reference)
#include <cuda_runtime.h>
#include <cuda_fp16.h>
#include <cstdint>
#include <cstddef>

typedef unsigned short ushort_t;

// ---------------------------------------------------------------------------
// Scratch (static __device__ arrays; allocation-free rule)
// ---------------------------------------------------------------------------
__device__ ushort_t g_qh  [(size_t)65536 * 1024];   // q  fp16
__device__ ushort_t g_kvh [(size_t)65536 * 2048];   // k|v fp16
__device__ ushort_t g_xh  [(size_t)65536 * 1024];   // x as fp16
__device__ ushort_t g_yh  [(size_t)65536 * 1024];   // y as fp16
__device__ ushort_t g_wvh [(size_t)65536 * 1024];   // attn*v as fp16
__device__ ushort_t g_wh  [4u * 1024u * 1024u];     // W^T fp16, [mat][n][k]

// ---------------------------------------------------------------------------
// Portable (sm_80-era) PTX helpers — valid on base sm_100 target.
// ---------------------------------------------------------------------------
__device__ __forceinline__ uint32_t smem_to_u32(const void* p) {
    uint32_t a;
    asm("{ .reg .u64 t; cvta.to.shared.u64 t, %1; cvt.u32.u64 %0, t; }" : "=r"(a) : "l"(p));
    return a;
}
__device__ __forceinline__ void cp_async16(uint32_t dst, const void* src) {
    asm volatile("cp.async.cg.shared.global [%0], [%1], 16;" :: "r"(dst), "l"(src));
}
#define CP_COMMIT()     asm volatile("cp.async.commit_group;" ::: "memory")
#define CP_WAIT(n)      asm volatile("cp.async.wait_group %0;" :: "n"(n) : "memory")

__device__ __forceinline__ void ldsm4(uint32_t* r, uint32_t addr) {
    asm volatile("ldmatrix.sync.aligned.m8n8.x4.shared.b16 {%0,%1,%2,%3}, [%4];"
                 : "=r"(r[0]), "=r"(r[1]), "=r"(r[2]), "=r"(r[3]) : "r"(addr));
}
__device__ __forceinline__ void mma16816(float* c, const uint32_t* a, const uint32_t* b) {
    asm volatile("mma.sync.aligned.m16n8k16.row.col.f32.f16.f16.f32 "
                 "{%0,%1,%2,%3}, {%4,%5,%6,%7}, {%8,%9}, {%0,%1,%2,%3};"
                 : "+f"(c[0]), "+f"(c[1]), "+f"(c[2]), "+f"(c[3])
                 : "r"(a[0]), "r"(a[1]), "r"(a[2]), "r"(a[3]), "r"(b[0]), "r"(b[1]));
}
__device__ __forceinline__ uint32_t f16x2_rn(float hi_val, float lo_val) {
    uint32_t r;
    asm("cvt.rn.f16x2.f32 %0, %1, %2;" : "=r"(r) : "f"(hi_val), "f"(lo_val));
    return r;    // low 16 bits = lo_val
}

// smem swizzle: XOR 16B-unit index (bits 4-6) with row%8 (bits 7-9). Rows = 128B.
// MUST be applied to the FULL byte offset (incl. the k-step term).
#define SW128(off) ((off) ^ (((off) >> 3) & 0x70))

// CTA tile 128x128: stage = A(16KB) + B(16KB) = 32KB; 3-ring = 96KB; 2 CTA/SM.
static constexpr uint32_t STAGE_BYTES = 32768;
static constexpr int SMEM_BYTES = 3 * 32768;

// ---------------------------------------------------------------------------
// No-op kernel: occupies launch slot #1 so ncu's sampled slot (#4) lands on
// k_gemm_qkv instead of k_attn (profiler steering; ~2us cost).
// ---------------------------------------------------------------------------
__global__ void k_nop() {}

// ---------------------------------------------------------------------------
// Activation convert: fp32 -> fp16, both x and y in one launch (blockIdx.y).
// ---------------------------------------------------------------------------
__global__ void k_cvt2(const float4* __restrict__ x, const float4* __restrict__ y,
                       uint2* __restrict__ xh, uint2* __restrict__ yh, int n4)
{
    int i = blockIdx.x * 256 + threadIdx.x;
    if (i >= n4) return;
    const float4* in = blockIdx.y ? y : x;
    uint2* out = blockIdx.y ? yh : xh;
    const float4 v = in[i];
    uint2 H;
    H.x = f16x2_rn(v.y, v.x);
    H.y = f16x2_rn(v.w, v.z);
    out[i] = H;
}

// ---------------------------------------------------------------------------
// Weight prep: Wt[mat][n][k] = fp16(W[k][n]) (transposed)
// ---------------------------------------------------------------------------
__global__ void k_prep_w(const float* __restrict__ Wq, const float* __restrict__ Wkv,
                         const float* __restrict__ Wproj)
{
    __shared__ float t[32][33];
    const int m = blockIdx.z;
    const float* src; int ld; int coff = 0;
    if (m == 0)      { src = Wq;    ld = 1024; }
    else if (m == 1) { src = Wkv;   ld = 2048; }
    else if (m == 2) { src = Wkv;   ld = 2048; coff = 1024; }
    else             { src = Wproj; ld = 1024; }
    const int n0 = blockIdx.x * 32, k0 = blockIdx.y * 32;
    const int tx = threadIdx.x, ty = threadIdx.y;
#pragma unroll
    for (int j = 0; j < 4; j++)
        t[ty + j * 8][tx] = src[(size_t)(k0 + ty + j * 8) * ld + coff + n0 + tx];
    __syncthreads();
    const size_t base = (size_t)m * 1048576u;
#pragma unroll
    for (int j = 0; j < 4; j++) {
        const int n = n0 + ty + j * 8;
        const int k = k0 + tx;
        g_wh[base + (size_t)n * 1024 + k] =
            __half_as_ushort(__float2half_rn(t[tx][ty + j * 8]));
    }
}

// ---------------------------------------------------------------------------
// Stage ONE QUARTER of a K=64 chunk (rows 32*part..32*part+31 of A and B).
// 4 cp.async per thread; spread across s-steps to smooth MIO pressure.
// Coalesced: 8-lane groups cover one FULL 128B gmem line per warp-instruction.
// ---------------------------------------------------------------------------
__device__ __forceinline__ void stage_part(
    uint32_t sbase, int buf, int kk, int part,
    const ushort_t* __restrict__ Ah, const ushort_t* __restrict__ Bh,
    size_t arow0, int tid)
{
    const int g = tid >> 3;             // 0..15: row group
    const int u = tid & 7;              // 16B unit within the 128B row-slice
    const uint32_t so = sbase + (uint32_t)buf * STAGE_BYTES;
#pragma unroll
    for (int pp = 0; pp < 2; pp++) {
        const int row = (part * 2 + pp) * 16 + g;
        const uint32_t dsw = SW128((uint32_t)(row * 128 + u * 16));
        cp_async16(so +          dsw, Ah + (arow0 + row) * 1024 + kk + u * 8);
        cp_async16(so + 16384u + dsw, Bh + (size_t)row * 1024 + kk + u * 8);
    }
}

// ---------------------------------------------------------------------------
// Core 128x128 GEMM tile: D = A_fp16 @ B_fp16^T.
// 4 warps (128 thr) as 2(m) x 2(n), warp tile 64x64; 2 CTAs/SM. 3-stage
// cp.async ring, one barrier per chunk. First fragment's LDSMs issue right
// after the barrier; the next chunk's cp.async are spread across s-steps
// (4/thread/step) instead of bursting 16 at the chunk head (MIO smoothing).
// ---------------------------------------------------------------------------
template <bool OUT16>
__device__ __forceinline__ void gemm_tile(
    const ushort_t* __restrict__ Ah, size_t arow0,
    const ushort_t* __restrict__ Bh,
    void* __restrict__ Cout, size_t ldc, int ccol, const float* __restrict__ bias)
{
    extern __shared__ char smem[];
    const uint32_t sbase = smem_to_u32(smem);
    const int tid = threadIdx.x, lane = tid & 31, wid = tid >> 5;
    const int wm = (wid & 1) * 64;        // 2 warp rows x 64
    const int wn = (wid >> 1) * 64;       // 2 warp cols x 64

    float acc[4][8][4];
#pragma unroll
    for (int i = 0; i < 4; i++)
#pragma unroll
        for (int j = 0; j < 8; j++)
#pragma unroll
            for (int k = 0; k < 4; k++) acc[i][j][k] = 0.f;

    // Unswizzled per-fragment offsets; k-step adds s*32 which stays inside the
    // 3-bit 16B-unit field (u0 in {0,1}) so SW128(full offset) is exact.
    uint32_t arow_off[4], brow_off[4];
#pragma unroll
    for (int im = 0; im < 4; im++) {
        const uint32_t row = wm + im * 16 + (lane & 15);
        arow_off[im] = row * 128 + ((lane >> 4) * 16);
    }
#pragma unroll
    for (int p = 0; p < 4; p++) {
        const uint32_t t4 = lane >> 3;
        const uint32_t n = wn + p * 16 + ((t4 >> 1) << 3) + (lane & 7);
        brow_off[p] = n * 128 + ((t4 & 1) * 16);
    }

#pragma unroll
    for (int part = 0; part < 4; part++) stage_part(sbase, 0, 0, part, Ah, Bh, arow0, tid);
    CP_COMMIT();
#pragma unroll
    for (int part = 0; part < 4; part++) stage_part(sbase, 1, 64, part, Ah, Bh, arow0, tid);
    CP_COMMIT();

    int buf = 0;
#pragma unroll 1
    for (int c = 0; c < 16; c++) {
        if (c < 15) { CP_WAIT(1); } else { CP_WAIT(0); }
        __syncthreads();
        const uint32_t so = sbase + (uint32_t)buf * STAGE_BYTES;
        int nb = buf + 2; if (nb >= 3) nb -= 3;
        const bool do_stage = (c < 14);

        // First fragment LDSMs immediately after the barrier (before any
        // cp.async of chunk c+2 can clog the MIO/LSU issue port).
        uint32_t afr[2][4][4], bfr[2][4][4];
#pragma unroll
        for (int im = 0; im < 4; im++) ldsm4(afr[0][im], so + SW128(arow_off[im]));
#pragma unroll
        for (int p = 0; p < 4; p++)  ldsm4(bfr[0][p], so + 16384u + SW128(brow_off[p]));

#pragma unroll
        for (int s = 0; s < 4; s++) {
            const int cur = s & 1, nxt = cur ^ 1;
            // Spread next-next chunk staging: one quarter per s-step.
            // (Still strictly after this chunk's barrier -> WAR-safe on the
            // ring buffer; commit after the last quarter keeps the one-group-
            // per-chunk ledger identical to before.)
            if (do_stage) {
                stage_part(sbase, nb, (c + 2) * 64, s, Ah, Bh, arow0, tid);
                if (s == 3) CP_COMMIT();
            }
            if (s < 3) {
                const uint32_t ko = (uint32_t)(s + 1) * 32;
#pragma unroll
                for (int im = 0; im < 4; im++)
                    ldsm4(afr[nxt][im], so + SW128(arow_off[im] + ko));
#pragma unroll
                for (int p = 0; p < 4; p++)
                    ldsm4(bfr[nxt][p], so + 16384u + SW128(brow_off[p] + ko));
            }
#pragma unroll
            for (int im = 0; im < 4; im++)
#pragma unroll
                for (int jn = 0; jn < 8; jn++)
                    mma16816(acc[im][jn], afr[cur][im], &bfr[cur][jn >> 1][(jn & 1) * 2]);
        }
        if (++buf == 3) buf = 0;
    }

    // Epilogue
#pragma unroll
    for (int im = 0; im < 4; im++) {
        const size_t m0 = arow0 + wm + im * 16 + (lane >> 2);
#pragma unroll
        for (int jn = 0; jn < 8; jn++) {
            const int col = ccol + wn + jn * 8 + (lane & 3) * 2;
            if (OUT16) {
                ushort_t* O = (ushort_t*)Cout;
                *(uint32_t*)(O + m0 * ldc + col)       = f16x2_rn(acc[im][jn][1], acc[im][jn][0]);
                *(uint32_t*)(O + (m0 + 8) * ldc + col) = f16x2_rn(acc[im][jn][3], acc[im][jn][2]);
            } else {
                float* O = (float*)Cout;
                float2 v0 = make_float2(acc[im][jn][0], acc[im][jn][1]);
                float2 v1 = make_float2(acc[im][jn][2], acc[im][jn][3]);
                const float2 bb = *(const float2*)(bias + col);
                v0.x += bb.x; v0.y += bb.y; v1.x += bb.x; v1.y += bb.y;
                *(float2*)(O + m0 * ldc + col) = v0;
                *(float2*)(O + (m0 + 8) * ldc + col) = v1;
            }
        }
    }
}

// ---------------------------------------------------------------------------
// GEMM kernels (128 threads, 2 CTAs/SM)
// ---------------------------------------------------------------------------
__global__ __launch_bounds__(128, 2) void k_gemm_qkv()
{
    const int ct = blockIdx.x;            // 0-7: q, 8-15: k, 16-23: v
    const size_t rt = blockIdx.y;
    const ushort_t* Ah = (ct < 8) ? g_xh : g_yh;
    const int mat = (ct < 8) ? 0 : ((ct < 16) ? 1 : 2);
    const int nc = (ct & 7) * 128;
    const ushort_t* Bh = g_wh + (size_t)mat * 1048576u + (size_t)nc * 1024;

    ushort_t* C; size_t ldc; int ccol;
    if (ct < 8)       { C = g_qh;  ldc = 1024; ccol = nc; }
    else if (ct < 16) { C = g_kvh; ldc = 2048; ccol = nc; }
    else              { C = g_kvh; ldc = 2048; ccol = 1024 + nc; }

    gemm_tile<true>(Ah, rt * 128, Bh, C, ldc, ccol, nullptr);
}

__global__ __launch_bounds__(128, 2) void k_gemm_proj(
    const float* __restrict__ bproj, float* __restrict__ out)
{
    const int ct = blockIdx.x;            // 0..7
    const size_t rt = blockIdx.y;
    const int nc = ct * 128;
    const ushort_t* Bh = g_wh + (size_t)3 * 1048576u + (size_t)nc * 1024;
    gemm_tile<false>(g_wvh, rt * 128, Bh, out, 1024, nc, bproj);
}

// ---------------------------------------------------------------------------
// dots + softmax(16 heads) + attn*v -> wv. ONE WARP PER ROW (at its HBM
// roofline per R11-R13 ncu: ~83us @ 75% DRAM — unchanged).
// ---------------------------------------------------------------------------
__device__ __forceinline__ float dot8h(uint4 a, uint4 b)
{
    const uint32_t* pa = &a.x;
    const uint32_t* pb = &b.x;
    float s = 0.f;
#pragma unroll
    for (int i = 0; i < 4; i++) {
        const float2 fa = __half22float2(*(const __half2*)&pa[i]);
        const float2 fb = __half22float2(*(const __half2*)&pb[i]);
        s += fa.x * fb.x + fa.y * fb.y;
    }
    return s;
}

__global__ __launch_bounds__(256) void k_attn()
{
    const int lane = threadIdx.x & 31;
    const int w = threadIdx.x >> 5;
    const size_t r = (size_t)blockIdx.x * 8 + w;
    const uint4* qp = (const uint4*)(g_qh  + r * 1024);
    const uint4* kp = (const uint4*)(g_kvh + r * 2048);
    const uint4* vp = (const uint4*)(g_kvh + r * 2048 + 1024);

    float d[4];
#pragma unroll
    for (int i = 0; i < 4; i++) {
        float p = dot8h(qp[i * 32 + lane], kp[i * 32 + lane]);
        p += __shfl_xor_sync(0xffffffffu, p, 1);
        p += __shfl_xor_sync(0xffffffffu, p, 2);
        p += __shfl_xor_sync(0xffffffffu, p, 4);
        d[i] = p * (1.0f / 64.0f);   // scale^2 (double-scale in reference)
    }

    float m = fmaxf(fmaxf(d[0], d[1]), fmaxf(d[2], d[3]));
    m = fmaxf(m, __shfl_xor_sync(0xffffffffu, m, 8));
    m = fmaxf(m, __shfl_xor_sync(0xffffffffu, m, 16));
    float e[4], S = 0.f;
#pragma unroll
    for (int i = 0; i < 4; i++) { e[i] = __expf(d[i] - m); S += e[i]; }
    S += __shfl_xor_sync(0xffffffffu, S, 8);
    S += __shfl_xor_sync(0xffffffffu, S, 16);
    const float inv = 1.0f / S;

    uint4* wp = (uint4*)(g_wvh + r * 1024);
#pragma unroll
    for (int i = 0; i < 4; i++) {
        const float a = e[i] * inv;
        const uint4 v = vp[i * 32 + lane];
        const uint32_t* pv = &v.x;
        uint4 o;
        uint32_t* po = &o.x;
#pragma unroll
        for (int j = 0; j < 4; j++) {
            const float2 fv = __half22float2(*(const __half2*)&pv[j]);
            po[j] = f16x2_rn(fv.y * a, fv.x * a);
        }
        wp[i * 32 + lane] = o;
    }
}

// ---------------------------------------------------------------------------
// Launch. Inputs: x, y, mask(unused), Wq, Wkv, Wproj, bproj
// ---------------------------------------------------------------------------
extern "C" void kernel_launch(void* const* d_in, const int* in_sizes, int n_in,
                              void* d_out, int out_size)
{
    const float* x     = (const float*)d_in[0];
    const float* y     = (const float*)d_in[1];
    const float* Wq    = (const float*)d_in[3];
    const float* Wkv   = (const float*)d_in[4];
    const float* Wproj = (const float*)d_in[5];
    const float* bproj = (const float*)d_in[6];
    float* out = (float*)d_out;

    const int B = in_sizes[0] / 1024;
    const int n4 = B * 1024 / 4;

    ushort_t *xh, *yh;
    cudaGetSymbolAddress((void**)&xh, g_xh);
    cudaGetSymbolAddress((void**)&yh, g_yh);

    cudaFuncSetAttribute(k_gemm_qkv,  cudaFuncAttributeMaxDynamicSharedMemorySize, SMEM_BYTES);
    cudaFuncSetAttribute(k_gemm_proj, cudaFuncAttributeMaxDynamicSharedMemorySize, SMEM_BYTES);

    k_nop<<<1, 32>>>();   // launch-slot shim: puts k_gemm_qkv in ncu's sampled slot
    k_cvt2<<<dim3((n4 + 255) / 256, 2), 256>>>((const float4*)x, (const float4*)y,
                                               (uint2*)xh, (uint2*)yh, n4);
    k_prep_w<<<dim3(32, 32, 4), dim3(32, 8)>>>(Wq, Wkv, Wproj);

    k_gemm_qkv<<<dim3(24, B / 128), 128, SMEM_BYTES>>>();
    k_attn<<<B / 8, 256>>>();
    k_gemm_proj<<<dim3(8, B / 128), 128, SMEM_BYTES>>>(bproj, out);
}

// round 17
// speedup vs baseline: 1.0148x; 1.0148x over previous
#include <cuda_runtime.h>
#include <cuda_fp16.h>
#include <cstdint>
#include <cstddef>

typedef unsigned short ushort_t;

// ---------------------------------------------------------------------------
// Scratch (static __device__ arrays; allocation-free rule)
// ---------------------------------------------------------------------------
__device__ ushort_t g_qh  [(size_t)65536 * 1024];   // q  fp16
__device__ ushort_t g_kvh [(size_t)65536 * 2048];   // k|v fp16
__device__ ushort_t g_xh  [(size_t)65536 * 1024];   // x as fp16
__device__ ushort_t g_yh  [(size_t)65536 * 1024];   // y as fp16
__device__ ushort_t g_wvh [(size_t)65536 * 1024];   // attn*v as fp16
__device__ ushort_t g_wh  [4u * 1024u * 1024u];     // W^T fp16, [mat][n][k]

// ---------------------------------------------------------------------------
// Portable (sm_80-era) PTX helpers — valid on base sm_100 target.
// ---------------------------------------------------------------------------
__device__ __forceinline__ uint32_t smem_to_u32(const void* p) {
    uint32_t a;
    asm("{ .reg .u64 t; cvta.to.shared.u64 t, %1; cvt.u32.u64 %0, t; }" : "=r"(a) : "l"(p));
    return a;
}
__device__ __forceinline__ void cp_async16(uint32_t dst, const void* src) {
    asm volatile("cp.async.cg.shared.global [%0], [%1], 16;" :: "r"(dst), "l"(src));
}
#define CP_COMMIT()     asm volatile("cp.async.commit_group;" ::: "memory")
#define CP_WAIT(n)      asm volatile("cp.async.wait_group %0;" :: "n"(n) : "memory")

__device__ __forceinline__ void ldsm4(uint32_t* r, uint32_t addr) {
    asm volatile("ldmatrix.sync.aligned.m8n8.x4.shared.b16 {%0,%1,%2,%3}, [%4];"
                 : "=r"(r[0]), "=r"(r[1]), "=r"(r[2]), "=r"(r[3]) : "r"(addr));
}
__device__ __forceinline__ void mma16816(float* c, const uint32_t* a, const uint32_t* b) {
    asm volatile("mma.sync.aligned.m16n8k16.row.col.f32.f16.f16.f32 "
                 "{%0,%1,%2,%3}, {%4,%5,%6,%7}, {%8,%9}, {%0,%1,%2,%3};"
                 : "+f"(c[0]), "+f"(c[1]), "+f"(c[2]), "+f"(c[3])
                 : "r"(a[0]), "r"(a[1]), "r"(a[2]), "r"(a[3]), "r"(b[0]), "r"(b[1]));
}
__device__ __forceinline__ uint32_t f16x2_rn(float hi_val, float lo_val) {
    uint32_t r;
    asm("cvt.rn.f16x2.f32 %0, %1, %2;" : "=r"(r) : "f"(hi_val), "f"(lo_val));
    return r;    // low 16 bits = lo_val
}

// smem swizzle: XOR 16B-unit index (bits 4-6) with row%8 (bits 7-9). Rows = 128B.
#define SW128(off) ((off) ^ (((off) >> 3) & 0x70))

// CTA tile 128x128: stage = A(16KB) + B(16KB) = 32KB; 3-ring = 96KB; 2 CTA/SM.
static constexpr uint32_t STAGE_BYTES = 32768;
static constexpr int SMEM_BYTES = 3 * 32768;

// Epilogue staging pitches (BOTH multiples of 16B — R16's 264 crashed):
//   fp16: 272 B = 17 x 16B units (odd -> STS banks r'*4+c' all distinct)
//   fp32: 528 B = 33 x 16B units
static constexpr int EPI_PITCH16 = 272;
static constexpr int EPI_PITCH32 = 528;

// ---------------------------------------------------------------------------
// No-op kernel: keeps k_gemm_qkv in ncu's sampled launch slot (#4).
// ---------------------------------------------------------------------------
__global__ void k_nop() {}

// ---------------------------------------------------------------------------
// Activation convert: fp32 -> fp16, both x and y in one launch (blockIdx.y).
// ---------------------------------------------------------------------------
__global__ void k_cvt2(const float4* __restrict__ x, const float4* __restrict__ y,
                       uint2* __restrict__ xh, uint2* __restrict__ yh, int n4)
{
    int i = blockIdx.x * 256 + threadIdx.x;
    if (i >= n4) return;
    const float4* in = blockIdx.y ? y : x;
    uint2* out = blockIdx.y ? yh : xh;
    const float4 v = in[i];
    uint2 H;
    H.x = f16x2_rn(v.y, v.x);
    H.y = f16x2_rn(v.w, v.z);
    out[i] = H;
}

// ---------------------------------------------------------------------------
// Weight prep: Wt[mat][n][k] = fp16(W[k][n]) (transposed)
// ---------------------------------------------------------------------------
__global__ void k_prep_w(const float* __restrict__ Wq, const float* __restrict__ Wkv,
                         const float* __restrict__ Wproj)
{
    __shared__ float t[32][33];
    const int m = blockIdx.z;
    const float* src; int ld; int coff = 0;
    if (m == 0)      { src = Wq;    ld = 1024; }
    else if (m == 1) { src = Wkv;   ld = 2048; }
    else if (m == 2) { src = Wkv;   ld = 2048; coff = 1024; }
    else             { src = Wproj; ld = 1024; }
    const int n0 = blockIdx.x * 32, k0 = blockIdx.y * 32;
    const int tx = threadIdx.x, ty = threadIdx.y;
#pragma unroll
    for (int j = 0; j < 4; j++)
        t[ty + j * 8][tx] = src[(size_t)(k0 + ty + j * 8) * ld + coff + n0 + tx];
    __syncthreads();
    const size_t base = (size_t)m * 1048576u;
#pragma unroll
    for (int j = 0; j < 4; j++) {
        const int n = n0 + ty + j * 8;
        const int k = k0 + tx;
        g_wh[base + (size_t)n * 1024 + k] =
            __half_as_ushort(__float2half_rn(t[tx][ty + j * 8]));
    }
}

// ---------------------------------------------------------------------------
// Stage ONE QUARTER of a K=64 chunk (rows 32*part..32*part+31 of A and B).
// 4 cp.async per thread; spread across s-steps to smooth MIO pressure.
// ---------------------------------------------------------------------------
__device__ __forceinline__ void stage_part(
    uint32_t sbase, int buf, int kk, int part,
    const ushort_t* __restrict__ Ah, const ushort_t* __restrict__ Bh,
    size_t arow0, int tid)
{
    const int g = tid >> 3;             // 0..15: row group
    const int u = tid & 7;              // 16B unit within the 128B row-slice
    const uint32_t so = sbase + (uint32_t)buf * STAGE_BYTES;
#pragma unroll
    for (int pp = 0; pp < 2; pp++) {
        const int row = (part * 2 + pp) * 16 + g;
        const uint32_t dsw = SW128((uint32_t)(row * 128 + u * 16));
        cp_async16(so +          dsw, Ah + (arow0 + row) * 1024 + kk + u * 8);
        cp_async16(so + 16384u + dsw, Bh + (size_t)row * 1024 + kk + u * 8);
    }
}

// ---------------------------------------------------------------------------
// Core 128x128 GEMM tile: D = A_fp16 @ B_fp16^T.
// 4 warps (2m x 2n), warp tile 64x64; 2 CTAs/SM. 3-stage cp.async ring.
// LDSM strictly AFTER the barrier (cp.async completion is per-warp: the
// barrier after every warp's CP_WAIT is what makes chunk c's data globally
// visible — R16's pre-barrier hoist was racy and is reverted).
// Swizzle masks are ko-invariant (ko<=96 never carries into bit 7) and
// precomputed: 2 ALU ops per LDSM address instead of 5.
// Epilogue staged through smem (16B-aligned pitches) for coalesced STG.128.
// ---------------------------------------------------------------------------
template <bool OUT16>
__device__ __forceinline__ void gemm_tile(
    const ushort_t* __restrict__ Ah, size_t arow0,
    const ushort_t* __restrict__ Bh,
    void* __restrict__ Cout, size_t ldc, int ccol, const float* __restrict__ bias)
{
    extern __shared__ char smem[];
    const uint32_t sbase = smem_to_u32(smem);
    const int tid = threadIdx.x, lane = tid & 31, wid = tid >> 5;
    const int wm = (wid & 1) * 64;        // 2 warp rows x 64
    const int wn = (wid >> 1) * 64;       // 2 warp cols x 64

    float acc[4][8][4];
#pragma unroll
    for (int i = 0; i < 4; i++)
#pragma unroll
        for (int j = 0; j < 8; j++)
#pragma unroll
            for (int k = 0; k < 4; k++) acc[i][j][k] = 0.f;

    // Unswizzled fragment offsets + ko-invariant swizzle masks.
    uint32_t arow_off[4], brow_off[4], amask[4], bmask[4];
#pragma unroll
    for (int im = 0; im < 4; im++) {
        const uint32_t row = wm + im * 16 + (lane & 15);
        arow_off[im] = row * 128 + ((lane >> 4) * 16);
        amask[im]   = (arow_off[im] >> 3) & 0x70;
    }
#pragma unroll
    for (int p = 0; p < 4; p++) {
        const uint32_t t4 = lane >> 3;
        const uint32_t n = wn + p * 16 + ((t4 >> 1) << 3) + (lane & 7);
        brow_off[p] = n * 128 + ((t4 & 1) * 16);
        bmask[p]    = (brow_off[p] >> 3) & 0x70;
    }

#pragma unroll
    for (int part = 0; part < 4; part++) stage_part(sbase, 0, 0, part, Ah, Bh, arow0, tid);
    CP_COMMIT();
#pragma unroll
    for (int part = 0; part < 4; part++) stage_part(sbase, 1, 64, part, Ah, Bh, arow0, tid);
    CP_COMMIT();

    int buf = 0;
#pragma unroll 1
    for (int c = 0; c < 16; c++) {
        if (c < 15) { CP_WAIT(1); } else { CP_WAIT(0); }
        __syncthreads();   // makes ALL warps' cp.async for chunk c visible
        const uint32_t so = sbase + (uint32_t)buf * STAGE_BYTES;
        int nb = buf + 2; if (nb >= 3) nb -= 3;
        const bool do_stage = (c < 14);

        uint32_t afr[2][4][4], bfr[2][4][4];
#pragma unroll
        for (int im = 0; im < 4; im++) ldsm4(afr[0][im], so + (arow_off[im] ^ amask[im]));
#pragma unroll
        for (int p = 0; p < 4; p++)  ldsm4(bfr[0][p], so + 16384u + (brow_off[p] ^ bmask[p]));

#pragma unroll
        for (int s = 0; s < 4; s++) {
            const int cur = s & 1, nxt = cur ^ 1;
            if (do_stage) {
                stage_part(sbase, nb, (c + 2) * 64, s, Ah, Bh, arow0, tid);
                if (s == 3) CP_COMMIT();
            }
            if (s < 3) {
                const uint32_t ko = (uint32_t)(s + 1) * 32;
#pragma unroll
                for (int im = 0; im < 4; im++)
                    ldsm4(afr[nxt][im], so + ((arow_off[im] + ko) ^ amask[im]));
#pragma unroll
                for (int p = 0; p < 4; p++)
                    ldsm4(bfr[nxt][p], so + 16384u + ((brow_off[p] + ko) ^ bmask[p]));
            }
#pragma unroll
            for (int im = 0; im < 4; im++)
#pragma unroll
                for (int jn = 0; jn < 8; jn++)
                    mma16816(acc[im][jn], afr[cur][im], &bfr[cur][jn >> 1][(jn & 1) * 2]);
        }
        if (++buf == 3) buf = 0;
    }

    // ---------- Epilogue: stage tile in smem, then coalesced STG.128 ----------
    __syncthreads();   // all warps done with mainloop LDSMs before smem reuse
    if (OUT16) {
#pragma unroll
        for (int im = 0; im < 4; im++) {
            const int m0r = wm + im * 16 + (lane >> 2);
#pragma unroll
            for (int jn = 0; jn < 8; jn++) {
                const int col = wn + jn * 8 + (lane & 3) * 2;
                *(uint32_t*)(smem + m0r * EPI_PITCH16 + col * 2) =
                    f16x2_rn(acc[im][jn][1], acc[im][jn][0]);
                *(uint32_t*)(smem + (m0r + 8) * EPI_PITCH16 + col * 2) =
                    f16x2_rn(acc[im][jn][3], acc[im][jn][2]);
            }
        }
        __syncthreads();
        ushort_t* O = (ushort_t*)Cout;
#pragma unroll
        for (int i = 0; i < 16; i++) {
            const int u = tid + i * 128;
            const int r = u >> 4, cu = u & 15;
            const uint4 v = *(const uint4*)(smem + r * EPI_PITCH16 + cu * 16);
            *(uint4*)(O + (arow0 + r) * ldc + ccol + cu * 8) = v;
        }
    } else {
#pragma unroll
        for (int im = 0; im < 4; im++) {
            const int m0r = wm + im * 16 + (lane >> 2);
#pragma unroll
            for (int jn = 0; jn < 8; jn++) {
                const int col = wn + jn * 8 + (lane & 3) * 2;
                const float2 bb = *(const float2*)(bias + ccol + col);
                *(float2*)(smem + m0r * EPI_PITCH32 + col * 4) =
                    make_float2(acc[im][jn][0] + bb.x, acc[im][jn][1] + bb.y);
                *(float2*)(smem + (m0r + 8) * EPI_PITCH32 + col * 4) =
                    make_float2(acc[im][jn][2] + bb.x, acc[im][jn][3] + bb.y);
            }
        }
        __syncthreads();
        float* O = (float*)Cout;
#pragma unroll
        for (int i = 0; i < 32; i++) {
            const int u = tid + i * 128;
            const int r = u >> 5, cu = u & 31;
            const uint4 v = *(const uint4*)(smem + r * EPI_PITCH32 + cu * 16);
            *(uint4*)(O + (arow0 + r) * ldc + ccol + cu * 4) = v;
        }
    }
}

// ---------------------------------------------------------------------------
// GEMM kernels (128 threads, 2 CTAs/SM)
// ---------------------------------------------------------------------------
__global__ __launch_bounds__(128, 2) void k_gemm_qkv()
{
    const int ct = blockIdx.x;            // 0-7: q, 8-15: k, 16-23: v
    const size_t rt = blockIdx.y;
    const ushort_t* Ah = (ct < 8) ? g_xh : g_yh;
    const int mat = (ct < 8) ? 0 : ((ct < 16) ? 1 : 2);
    const int nc = (ct & 7) * 128;
    const ushort_t* Bh = g_wh + (size_t)mat * 1048576u + (size_t)nc * 1024;

    ushort_t* C; size_t ldc; int ccol;
    if (ct < 8)       { C = g_qh;  ldc = 1024; ccol = nc; }
    else if (ct < 16) { C = g_kvh; ldc = 2048; ccol = nc; }
    else              { C = g_kvh; ldc = 2048; ccol = 1024 + nc; }

    gemm_tile<true>(Ah, rt * 128, Bh, C, ldc, ccol, nullptr);
}

__global__ __launch_bounds__(128, 2) void k_gemm_proj(
    const float* __restrict__ bproj, float* __restrict__ out)
{
    const int ct = blockIdx.x;            // 0..7
    const size_t rt = blockIdx.y;
    const int nc = ct * 128;
    const ushort_t* Bh = g_wh + (size_t)3 * 1048576u + (size_t)nc * 1024;
    gemm_tile<false>(g_wvh, rt * 128, Bh, out, 1024, nc, bproj);
}

// ---------------------------------------------------------------------------
// dots + softmax(16 heads) + attn*v -> wv. ONE WARP PER ROW (at its HBM
// roofline per R11-R13 ncu: ~83us @ 75% DRAM — unchanged).
// ---------------------------------------------------------------------------
__device__ __forceinline__ float dot8h(uint4 a, uint4 b)
{
    const uint32_t* pa = &a.x;
    const uint32_t* pb = &b.x;
    float s = 0.f;
#pragma unroll
    for (int i = 0; i < 4; i++) {
        const float2 fa = __half22float2(*(const __half2*)&pa[i]);
        const float2 fb = __half22float2(*(const __half2*)&pb[i]);
        s += fa.x * fb.x + fa.y * fb.y;
    }
    return s;
}

__global__ __launch_bounds__(256) void k_attn()
{
    const int lane = threadIdx.x & 31;
    const int w = threadIdx.x >> 5;
    const size_t r = (size_t)blockIdx.x * 8 + w;
    const uint4* qp = (const uint4*)(g_qh  + r * 1024);
    const uint4* kp = (const uint4*)(g_kvh + r * 2048);
    const uint4* vp = (const uint4*)(g_kvh + r * 2048 + 1024);

    float d[4];
#pragma unroll
    for (int i = 0; i < 4; i++) {
        float p = dot8h(qp[i * 32 + lane], kp[i * 32 + lane]);
        p += __shfl_xor_sync(0xffffffffu, p, 1);
        p += __shfl_xor_sync(0xffffffffu, p, 2);
        p += __shfl_xor_sync(0xffffffffu, p, 4);
        d[i] = p * (1.0f / 64.0f);   // scale^2 (double-scale in reference)
    }

    float m = fmaxf(fmaxf(d[0], d[1]), fmaxf(d[2], d[3]));
    m = fmaxf(m, __shfl_xor_sync(0xffffffffu, m, 8));
    m = fmaxf(m, __shfl_xor_sync(0xffffffffu, m, 16));
    float e[4], S = 0.f;
#pragma unroll
    for (int i = 0; i < 4; i++) { e[i] = __expf(d[i] - m); S += e[i]; }
    S += __shfl_xor_sync(0xffffffffu, S, 8);
    S += __shfl_xor_sync(0xffffffffu, S, 16);
    const float inv = 1.0f / S;

    uint4* wp = (uint4*)(g_wvh + r * 1024);
#pragma unroll
    for (int i = 0; i < 4; i++) {
        const float a = e[i] * inv;
        const uint4 v = vp[i * 32 + lane];
        const uint32_t* pv = &v.x;
        uint4 o;
        uint32_t* po = &o.x;
#pragma unroll
        for (int j = 0; j < 4; j++) {
            const float2 fv = __half22float2(*(const __half2*)&pv[j]);
            po[j] = f16x2_rn(fv.y * a, fv.x * a);
        }
        wp[i * 32 + lane] = o;
    }
}

// ---------------------------------------------------------------------------
// Launch. Inputs: x, y, mask(unused), Wq, Wkv, Wproj, bproj
// ---------------------------------------------------------------------------
extern "C" void kernel_launch(void* const* d_in, const int* in_sizes, int n_in,
                              void* d_out, int out_size)
{
    const float* x     = (const float*)d_in[0];
    const float* y     = (const float*)d_in[1];
    const float* Wq    = (const float*)d_in[3];
    const float* Wkv   = (const float*)d_in[4];
    const float* Wproj = (const float*)d_in[5];
    const float* bproj = (const float*)d_in[6];
    float* out = (float*)d_out;

    const int B = in_sizes[0] / 1024;
    const int n4 = B * 1024 / 4;

    ushort_t *xh, *yh;
    cudaGetSymbolAddress((void**)&xh, g_xh);
    cudaGetSymbolAddress((void**)&yh, g_yh);

    cudaFuncSetAttribute(k_gemm_qkv,  cudaFuncAttributeMaxDynamicSharedMemorySize, SMEM_BYTES);
    cudaFuncSetAttribute(k_gemm_proj, cudaFuncAttributeMaxDynamicSharedMemorySize, SMEM_BYTES);

    k_nop<<<1, 32>>>();   // launch-slot shim: keeps k_gemm_qkv in ncu's sampled slot
    k_cvt2<<<dim3((n4 + 255) / 256, 2), 256>>>((const float4*)x, (const float4*)y,
                                               (uint2*)xh, (uint2*)yh, n4);
    k_prep_w<<<dim3(32, 32, 4), dim3(32, 8)>>>(Wq, Wkv, Wproj);

    k_gemm_qkv<<<dim3(24, B / 128), 128, SMEM_BYTES>>>();
    k_attn<<<B / 8, 256>>>();
    k_gemm_proj<<<dim3(8, B / 128), 128, SMEM_BYTES>>>(bproj, out);
}